// round 14
// baseline (speedup 1.0000x reference)
#include <cuda_runtime.h>
#include <cuda_fp16.h>
#include <cstdint>

// NAryTreeLSTMCell — round 14: 4-stage (BK=32) bulk-DMA pipeline.
// r13 showed the chunk-boundary refill latency is exposed with 2-deep stages:
// stage s refill (after all 8 warps consume chunk k) must finish within one
// chunk-time. 4 stages give the DMA ~3 chunk-times of slack and halve the
// boundary quantum. Same SMEM budget -> still 2 CTAs/SM. Math identical.
// ARITY=2, LABEL_DIM=128, H_DIM=512, B=16384, ARG_DIM=1152.

namespace {
constexpr int Bsz = 16384;
constexpr int H   = 512;
constexpr int L   = 128;
constexpr int K   = 1152;
constexpr int NG  = 5;
constexpr int BM  = 64;            // batch rows / CTA
constexpr int BNR = 320;           // B rows: 5 gates x 64 h
constexpr int BHh = 64;            // h per gate per CTA
constexpr int BK  = 32;            // K per chunk
constexpr int NCHUNK = K / BK;     // 36
constexpr int NSTG = 4;
constexpr int THREADS = 256;       // 8 warps: 2(m) x 4(n), warp tile 32x80

constexpr uint32_t AG = BM * 16;    // 1024 (granule stride in A tile)
constexpr uint32_t BG = BNR * 16;   // 5120
constexpr uint32_t A_TILE = 4 * AG;                // 4096 B  (4 granules/chunk)
constexpr uint32_t B_TILE = 4 * BG;                // 20480 B
constexpr uint32_t OFF_A = 0;
constexpr uint32_t OFF_B = A_TILE;
constexpr uint32_t STAGE_BYTES = A_TILE + B_TILE;  // 24576
constexpr uint32_t SMEM_TOTAL  = NSTG * STAGE_BYTES + 128;  // 98432 -> 2 CTAs/SM

constexpr int NX = Bsz * (K / 4);
constexpr int NW = NG * H * (K / 4);
} // namespace

// ---- scratch: chunk-tiled, granule-blocked images (exact SMEM layout) ----
__device__ __half g_Xt[(size_t)NCHUNK * (Bsz / BM) * (A_TILE / 2)];
__device__ __half g_Wt[(size_t)NCHUNK * (H / BHh) * (B_TILE / 2)];

// ---- PTX helpers ----
__device__ __forceinline__ uint32_t smem_u32(const void* p) {
    return (uint32_t)__cvta_generic_to_shared(p);
}
__device__ __forceinline__ void bulk_cp(uint32_t dst, const void* src,
                                        uint32_t bytes, uint32_t mbar) {
    asm volatile("cp.async.bulk.shared::cta.global.mbarrier::complete_tx::bytes "
                 "[%0], [%1], %2, [%3];"
                 :: "r"(dst), "l"(src), "r"(bytes), "r"(mbar) : "memory");
}
__device__ __forceinline__ void mbar_init(uint32_t a, uint32_t cnt) {
    asm volatile("mbarrier.init.shared.b64 [%0], %1;" :: "r"(a), "r"(cnt) : "memory");
}
__device__ __forceinline__ void mbar_expect(uint32_t a, uint32_t bytes) {
    asm volatile("mbarrier.arrive.expect_tx.shared::cta.b64 _, [%0], %1;"
                 :: "r"(a), "r"(bytes) : "memory");
}
__device__ __forceinline__ void mbar_arrive(uint32_t a) {
    asm volatile("mbarrier.arrive.shared::cta.b64 _, [%0];" :: "r"(a) : "memory");
}
__device__ __forceinline__ void mbar_wait(uint32_t a, uint32_t ph) {
    asm volatile("{\n.reg .pred P;\nLW%=:\n"
                 "mbarrier.try_wait.parity.shared::cta.b64 P, [%0], %1;\n"
                 "@!P bra LW%=;\n}" :: "r"(a), "r"(ph) : "memory");
}
__device__ __forceinline__ void ldsm4(uint32_t* r, uint32_t a) {
    asm volatile("ldmatrix.sync.aligned.m8n8.x4.shared.b16 {%0,%1,%2,%3}, [%4];"
                 : "=r"(r[0]), "=r"(r[1]), "=r"(r[2]), "=r"(r[3]) : "r"(a));
}
__device__ __forceinline__ void mma_f16(float* c, const uint32_t* a, const uint32_t* b) {
    asm volatile("mma.sync.aligned.m16n8k16.row.col.f32.f16.f16.f32 "
                 "{%0,%1,%2,%3}, {%4,%5,%6,%7}, {%8,%9}, {%0,%1,%2,%3};"
                 : "+f"(c[0]), "+f"(c[1]), "+f"(c[2]), "+f"(c[3])
                 : "r"(a[0]), "r"(a[1]), "r"(a[2]), "r"(a[3]), "r"(b[0]), "r"(b[1]));
}
__device__ __forceinline__ float sigmf(float x) { return 1.0f / (1.0f + __expf(-x)); }

// ---- merged pack kernel: fp32 -> fp16 tile images (32-K chunk granularity) ----
__global__ void pack_all(const float* __restrict__ label, const float* __restrict__ ch_h,
                         const float* __restrict__ Wi, const float* __restrict__ Wo,
                         const float* __restrict__ Wu, const float* __restrict__ Wfl,
                         const float* __restrict__ Wfs) {
    int i = blockIdx.x * blockDim.x + threadIdx.x;
    if (i < NX) {
        int b = i / (K / 4);
        int d = (i % (K / 4)) * 4;
        const float* src;
        if (d < L) src = label + (size_t)b * L + d;
        else {
            int dd = d - L; int j = dd >> 9; int hh = dd & 511;
            src = ch_h + (((size_t)(j * Bsz + b)) << 9) + hh;
        }
        float4 v = *reinterpret_cast<const float4*>(src);
        __half h4[4] = {__float2half_rn(v.x), __float2half_rn(v.y),
                        __float2half_rn(v.z), __float2half_rn(v.w)};
        int c  = d >> 5, kk = d & 31, g = kk >> 3;     // 36 chunks, 4 granules
        int mt = b >> 6, r = b & 63;                   // 256 m-tiles of 64 rows
        size_t o = ((size_t)(c * 256 + mt)) * (A_TILE / 2)
                 + (size_t)g * 512 + r * 8 + (kk & 7);
        *reinterpret_cast<uint2*>(&g_Xt[o]) = *reinterpret_cast<uint2*>(h4);
    } else if (i < NX + NW) {
        int u  = i - NX;
        int rw = u / (K / 4);
        int d  = (u % (K / 4)) * 4;
        int gate = rw >> 9, h = rw & 511;
        const float* src;
        if (gate == 0)      src = Wi + (size_t)h * K + d;
        else if (gate == 1) src = Wo + (size_t)h * K + d;
        else if (gate == 2) src = Wu + (size_t)h * K + d;
        else if (d < L)     src = Wfl + (size_t)h * L + d;
        else {
            int dd = d - L; int j = dd >> 9; int hh = dd & 511;
            src = Wfs + (((size_t)(((gate - 3) * 2 + j) * H + h)) << 9) + hh;
        }
        float4 v = *reinterpret_cast<const float4*>(src);
        __half h4[4] = {__float2half_rn(v.x), __float2half_rn(v.y),
                        __float2half_rn(v.z), __float2half_rn(v.w)};
        int c   = d >> 5, kk = d & 31, g = kk >> 3;
        int bht = h >> 6;
        int rr  = gate * 64 + (h & 63);
        size_t o = ((size_t)(c * 8 + bht)) * (B_TILE / 2)
                 + (size_t)g * 2560 + rr * 8 + (kk & 7);
        *reinterpret_cast<uint2*>(&g_Wt[o]) = *reinterpret_cast<uint2*>(h4);
    }
}

// ---- main kernel ----
__global__ __launch_bounds__(THREADS, 2)
void treelstm_mma(const float* __restrict__ ch_c,
                  const float* __restrict__ b_i, const float* __restrict__ b_o,
                  const float* __restrict__ b_u, const float* __restrict__ fbias,
                  float* __restrict__ out) {
    extern __shared__ char smem[];
    const uint32_t sbase = smem_u32(smem);
    const int tid  = threadIdx.x;
    const int wid  = tid >> 5, lane = tid & 31;
    const int wm   = wid & 1;          // 2 m-warps (32 rows each)
    const int wn   = wid >> 1;         // 4 n-warps (80 cols each)
    const int bht  = blockIdx.x;
    const int mt   = blockIdx.y;
    const int bh0  = bht * BHh;
    const int bm0  = mt * BM;

    const uint32_t STG  = sbase;
    const uint32_t MBF  = sbase + NSTG * STAGE_BYTES;     // 4 full barriers (tx)
    const uint32_t MBE  = MBF + NSTG * 8;                 // 4 empty barriers (8 arr)

    const char* Abase = reinterpret_cast<const char*>(g_Xt);
    const char* Bbase = reinterpret_cast<const char*>(g_Wt);
    auto Asrc = [&](int c) { return Abase + ((size_t)(c * 256 + mt)) * A_TILE; };
    auto Bsrc = [&](int c) { return Bbase + ((size_t)(c * 8 + bht)) * B_TILE; };

    if (tid == 0) {
        #pragma unroll
        for (int s = 0; s < NSTG; s++) {
            mbar_init(MBF + s * 8, 1);
            mbar_init(MBE + s * 8, 8);
        }
    }
    __syncthreads();
    if (tid == 0) {
        #pragma unroll
        for (int s = 0; s < NSTG; s++) {
            mbar_expect(MBF + s * 8, STAGE_BYTES);
            bulk_cp(STG + s * STAGE_BYTES + OFF_A, Asrc(s), A_TILE, MBF + s * 8);
            bulk_cp(STG + s * STAGE_BYTES + OFF_B, Bsrc(s), B_TILE, MBF + s * 8);
        }
    }

    // ldmatrix lane addressing (granule-blocked, no swizzle)
    const int ar  = ((lane >> 3) & 1) * 8 + (lane & 7);
    const uint32_t aBase = (uint32_t)((wm * 32 + ar) * 16) + (uint32_t)(lane >> 4) * AG;
    const int br  = ((lane >> 4) & 1) * 8 + (lane & 7);
    const uint32_t bBase = (uint32_t)((wn * 80 + br) * 16) + (uint32_t)((lane >> 3) & 1) * BG;

    float acc[2][10][4];               // warp tile 32x80, fp32 masters
    #pragma unroll
    for (int mi = 0; mi < 2; mi++)
        #pragma unroll
        for (int ni = 0; ni < 10; ni++)
            #pragma unroll
            for (int q = 0; q < 4; q++) acc[mi][ni][q] = 0.0f;

    uint32_t phf = 0, phe = 0;         // per-stage phase bitmasks
    for (int k = 0; k < NCHUNK; k++) {
        const int s = k & 3;
        const uint32_t stg  = STG + (uint32_t)s * STAGE_BYTES;
        const uint32_t mbf  = MBF + (uint32_t)s * 8;
        mbar_wait(mbf, (phf >> s) & 1);
        phf ^= (1u << s);

        // 10 iterations (2 ks x 5 np), one-deep operand ping-pong
        uint32_t A[2][8], Bf[2][4];
        ldsm4(A[0] + 0, stg + OFF_A + aBase);
        ldsm4(A[0] + 4, stg + OFF_A + aBase + 256);
        ldsm4(Bf[0],    stg + OFF_B + bBase);
        #pragma unroll
        for (int it = 0; it < 10; it++) {
            const int ks = it / 5, np = it % 5;
            const int ca = ks & 1, cb = it & 1;
            if (it + 1 < 10) {
                const int ks2 = (it + 1) / 5, np2 = (it + 1) % 5;
                ldsm4(Bf[1 - cb], stg + OFF_B + bBase
                                  + (uint32_t)(2 * ks2) * BG + (uint32_t)np2 * 256);
                if (np2 == 0) {
                    const uint32_t aA = stg + OFF_A + aBase + (uint32_t)(2 * ks2) * AG;
                    ldsm4(A[1 - ca] + 0, aA);
                    ldsm4(A[1 - ca] + 4, aA + 256);
                }
            }
            mma_f16(acc[0][np*2+0], A[ca] + 0, Bf[cb] + 0);
            mma_f16(acc[0][np*2+1], A[ca] + 0, Bf[cb] + 2);
            mma_f16(acc[1][np*2+0], A[ca] + 4, Bf[cb] + 0);
            mma_f16(acc[1][np*2+1], A[ca] + 4, Bf[cb] + 2);
        }
        // this warp done with stage s
        if (lane == 0) mbar_arrive(MBE + s * 8);
        // producer: once all 8 warps are done, refill stage s for chunk k+4
        if (tid == 0 && k + NSTG < NCHUNK) {
            mbar_wait(MBE + s * 8, (phe >> s) & 1);
            phe ^= (1u << s);
            mbar_expect(mbf, STAGE_BYTES);
            bulk_cp(stg + OFF_A, Asrc(k + NSTG), A_TILE, mbf);
            bulk_cp(stg + OFF_B, Bsrc(k + NSTG), B_TILE, mbf);
        }
    }

    // ---- epilogue: recombine gates through SMEM ----
    __syncthreads();                    // all warps out of mainloop
    float* gbuf = reinterpret_cast<float*>(smem);   // [320][65] = 83KB, fits
    #pragma unroll
    for (int mi = 0; mi < 2; mi++)
        #pragma unroll
        for (int ni = 0; ni < 10; ni++) {
            const int m = wm * 32 + mi * 16 + (lane >> 2);
            const int n = wn * 80 + ni * 8 + 2 * (lane & 3);
            gbuf[(size_t)n * 65 + m]           = acc[mi][ni][0];
            gbuf[(size_t)(n + 1) * 65 + m]     = acc[mi][ni][1];
            gbuf[(size_t)n * 65 + m + 8]       = acc[mi][ni][2];
            gbuf[(size_t)(n + 1) * 65 + m + 8] = acc[mi][ni][3];
        }
    __syncthreads();

    for (int idx = tid; idx < BM * BHh; idx += THREADS) {
        const int m = idx >> 6, h = idx & 63;
        const int hg = bh0 + h;
        const int b  = bm0 + m;
        const float vi = gbuf[(size_t)(0 * 64 + h) * 65 + m];
        const float vo = gbuf[(size_t)(1 * 64 + h) * 65 + m];
        const float vu = gbuf[(size_t)(2 * 64 + h) * 65 + m];
        const float v0 = gbuf[(size_t)(3 * 64 + h) * 65 + m];
        const float v1 = gbuf[(size_t)(4 * 64 + h) * 65 + m];
        const float ig = sigmf(vi + __ldg(&b_i[hg]));
        const float og = sigmf(vo + __ldg(&b_o[hg]));
        const float ug = tanhf(vu + __ldg(&b_u[hg]));
        const float f0 = sigmf(v0);
        const float f1 = sigmf(v1);
        const float c0 = ch_c[(size_t)b * H + hg];
        const float c1 = ch_c[(size_t)(Bsz + b) * H + hg];
        const float fb = __ldg(&fbias[hg]);
        const float nc = fmaf(ig, ug, fmaf(f0, c0, fmaf(f1, c1, fb * (c0 + c1))));
        const size_t o = (size_t)b * H + hg;
        out[o] = nc;
        out[(size_t)Bsz * H + o] = tanhf(og * nc);
    }
}

extern "C" void kernel_launch(void* const* d_in, const int* in_sizes, int n_in,
                              void* d_out, int out_size) {
    const float* label = (const float*)d_in[0];
    const float* ch_h  = (const float*)d_in[1];
    const float* ch_c  = (const float*)d_in[2];
    const float* W_i   = (const float*)d_in[3];
    const float* b_i   = (const float*)d_in[4];
    const float* W_o   = (const float*)d_in[5];
    const float* b_o   = (const float*)d_in[6];
    const float* W_u   = (const float*)d_in[7];
    const float* b_u   = (const float*)d_in[8];
    const float* W_fl  = (const float*)d_in[9];
    const float* W_fs  = (const float*)d_in[10];
    const float* fb    = (const float*)d_in[11];

    pack_all<<<(NX + NW + 255) / 256, 256>>>(label, ch_h, W_i, W_o, W_u, W_fl, W_fs);

    cudaFuncSetAttribute(treelstm_mma, cudaFuncAttributeMaxDynamicSharedMemorySize, SMEM_TOTAL);
    dim3 grid(H / BHh, Bsz / BM);   // (8, 256), 2 CTAs/SM
    treelstm_mma<<<grid, THREADS, SMEM_TOTAL>>>(ch_c, b_i, b_o, b_u, fb, (float*)d_out);
}

// round 16
// speedup vs baseline: 1.0696x; 1.0696x over previous
#include <cuda_runtime.h>
#include <cuda_fp16.h>
#include <cstdint>

// NAryTreeLSTMCell — round 15: r13 config (BK=64, 2 stages, 2 CTAs/SM, warp-
// granular full/empty mbarriers) + (a) operand-fragment pipelining carried
// ACROSS chunk boundaries (kills the 18 per-chunk serial ldsm prologues),
// (b) smem-staged fully-coalesced pack kernel.
// ARITY=2, LABEL_DIM=128, H_DIM=512, B=16384, ARG_DIM=1152.

namespace {
constexpr int Bsz = 16384;
constexpr int H   = 512;
constexpr int L   = 128;
constexpr int K   = 1152;
constexpr int NG  = 5;
constexpr int BM  = 64;            // batch rows / CTA
constexpr int BNR = 320;           // B rows: 5 gates x 64 h
constexpr int BHh = 64;            // h per gate per CTA
constexpr int BK  = 64;            // K per chunk
constexpr int NCHUNK = K / BK;     // 18
constexpr int THREADS = 256;       // 8 warps: 2(m) x 4(n), warp tile 32x80

constexpr uint32_t AG = BM * 16;    // 1024
constexpr uint32_t BG = BNR * 16;   // 5120
constexpr uint32_t A_TILE = 8 * AG;                // 8192 B
constexpr uint32_t B_TILE = 8 * BG;                // 40960 B
constexpr uint32_t OFF_A = 0;
constexpr uint32_t OFF_B = A_TILE;
constexpr uint32_t STAGE_BYTES = A_TILE + B_TILE;  // 49152
constexpr uint32_t SMEM_TOTAL  = 2 * STAGE_BYTES + 64;   // 98368 -> 2 CTAs/SM

constexpr int NXB = NCHUNK * (Bsz / BM);   // 4608 X pack blocks
constexpr int NWB = NCHUNK * (H / BHh);    // 144  W pack blocks
constexpr uint32_t PACK_SMEM = 8 * 5136;   // 41088 (W path; X uses 8*1040)
} // namespace

// ---- scratch: chunk-tiled, granule-blocked images (exact SMEM layout) ----
__device__ __half g_Xt[(size_t)NCHUNK * (Bsz / BM) * (A_TILE / 2)];
__device__ __half g_Wt[(size_t)NCHUNK * (H / BHh) * (B_TILE / 2)];

// ---- PTX helpers ----
__device__ __forceinline__ uint32_t smem_u32(const void* p) {
    return (uint32_t)__cvta_generic_to_shared(p);
}
__device__ __forceinline__ void bulk_cp(uint32_t dst, const void* src,
                                        uint32_t bytes, uint32_t mbar) {
    asm volatile("cp.async.bulk.shared::cta.global.mbarrier::complete_tx::bytes "
                 "[%0], [%1], %2, [%3];"
                 :: "r"(dst), "l"(src), "r"(bytes), "r"(mbar) : "memory");
}
__device__ __forceinline__ void mbar_init(uint32_t a, uint32_t cnt) {
    asm volatile("mbarrier.init.shared.b64 [%0], %1;" :: "r"(a), "r"(cnt) : "memory");
}
__device__ __forceinline__ void mbar_expect(uint32_t a, uint32_t bytes) {
    asm volatile("mbarrier.arrive.expect_tx.shared::cta.b64 _, [%0], %1;"
                 :: "r"(a), "r"(bytes) : "memory");
}
__device__ __forceinline__ void mbar_arrive(uint32_t a) {
    asm volatile("mbarrier.arrive.shared::cta.b64 _, [%0];" :: "r"(a) : "memory");
}
__device__ __forceinline__ void mbar_wait(uint32_t a, uint32_t ph) {
    asm volatile("{\n.reg .pred P;\nLW%=:\n"
                 "mbarrier.try_wait.parity.shared::cta.b64 P, [%0], %1;\n"
                 "@!P bra LW%=;\n}" :: "r"(a), "r"(ph) : "memory");
}
__device__ __forceinline__ void ldsm4(uint32_t* r, uint32_t a) {
    asm volatile("ldmatrix.sync.aligned.m8n8.x4.shared.b16 {%0,%1,%2,%3}, [%4];"
                 : "=r"(r[0]), "=r"(r[1]), "=r"(r[2]), "=r"(r[3]) : "r"(a));
}
__device__ __forceinline__ void mma_f16(float* c, const uint32_t* a, const uint32_t* b) {
    asm volatile("mma.sync.aligned.m16n8k16.row.col.f32.f16.f16.f32 "
                 "{%0,%1,%2,%3}, {%4,%5,%6,%7}, {%8,%9}, {%0,%1,%2,%3};"
                 : "+f"(c[0]), "+f"(c[1]), "+f"(c[2]), "+f"(c[3])
                 : "r"(a[0]), "r"(a[1]), "r"(a[2]), "r"(a[3]), "r"(b[0]), "r"(b[1]));
}
__device__ __forceinline__ float sigmf(float x) { return 1.0f / (1.0f + __expf(-x)); }

// ---- tiled pack: coalesced reads -> smem staging (padded) -> contiguous writes ----
__global__ void pack_all(const float* __restrict__ label, const float* __restrict__ ch_h,
                         const float* __restrict__ Wi, const float* __restrict__ Wo,
                         const float* __restrict__ Wu, const float* __restrict__ Wfl,
                         const float* __restrict__ Wfs) {
    extern __shared__ char ps[];
    const int bx = blockIdx.x;
    const int tid = threadIdx.x;
    if (bx < NXB) {
        // ---- X tile: (chunk c, m-tile mt) = 64 rows x 64 k ----
        const int c  = bx % NCHUNK, mt = bx / NCHUNK;
        const int k0 = c * BK, bm0 = mt * BM;
        #pragma unroll
        for (int j = 0; j < 4; j++) {
            const int i = tid + j * 256;       // 1024 float4
            const int r = i >> 4, q = i & 15;
            const int d = k0 + q * 4;
            const float* src;
            if (d < L) src = label + (size_t)(bm0 + r) * L + d;
            else {
                const int dd = d - L, ch = dd >> 9, hh = dd & 511;
                src = ch_h + (((size_t)(ch * Bsz + bm0 + r)) << 9) + hh;
            }
            const float4 v = *reinterpret_cast<const float4*>(src);
            __half h4[4] = {__float2half_rn(v.x), __float2half_rn(v.y),
                            __float2half_rn(v.z), __float2half_rn(v.w)};
            const int kk = q * 4, g = kk >> 3;
            *reinterpret_cast<uint2*>(ps + g * 1040 + r * 16 + (kk & 7) * 2) =
                *reinterpret_cast<uint2*>(h4);
        }
        __syncthreads();
        char* dst = reinterpret_cast<char*>(g_Xt) + ((size_t)(c * 256 + mt)) * A_TILE;
        #pragma unroll
        for (int j = 0; j < 2; j++) {
            const int idx = tid + j * 256;     // 512 x 16B
            const int g = idx >> 6, o = (idx & 63) * 16;
            *reinterpret_cast<uint4*>(dst + (size_t)idx * 16) =
                *reinterpret_cast<uint4*>(ps + g * 1040 + o);
        }
    } else {
        // ---- W tile: (chunk c, h-tile bht) = 320 rows x 64 k ----
        const int u  = bx - NXB;
        const int c  = u % NCHUNK, bht = u / NCHUNK;
        const int k0 = c * BK;
        #pragma unroll
        for (int j = 0; j < 20; j++) {
            const int i = tid + j * 256;       // 5120 float4
            const int rr = i >> 4, q = i & 15;
            const int gate = rr >> 6, h = bht * 64 + (rr & 63);
            const int d = k0 + q * 4;
            const float* src;
            if (gate == 0)      src = Wi + (size_t)h * K + d;
            else if (gate == 1) src = Wo + (size_t)h * K + d;
            else if (gate == 2) src = Wu + (size_t)h * K + d;
            else if (d < L)     src = Wfl + (size_t)h * L + d;
            else {
                const int dd = d - L, ch = dd >> 9, hh = dd & 511;
                src = Wfs + (((size_t)(((gate - 3) * 2 + ch) * H + h)) << 9) + hh;
            }
            const float4 v = *reinterpret_cast<const float4*>(src);
            __half h4[4] = {__float2half_rn(v.x), __float2half_rn(v.y),
                            __float2half_rn(v.z), __float2half_rn(v.w)};
            const int kk = q * 4, g = kk >> 3;
            *reinterpret_cast<uint2*>(ps + g * 5136 + rr * 16 + (kk & 7) * 2) =
                *reinterpret_cast<uint2*>(h4);
        }
        __syncthreads();
        char* dst = reinterpret_cast<char*>(g_Wt) + ((size_t)(c * 8 + bht)) * B_TILE;
        #pragma unroll
        for (int j = 0; j < 10; j++) {
            const int idx = tid + j * 256;     // 2560 x 16B
            const int g = idx / 320, o = (idx % 320) * 16;
            *reinterpret_cast<uint4*>(dst + (size_t)idx * 16) =
                *reinterpret_cast<uint4*>(ps + g * 5136 + o);
        }
    }
}

// ---- main kernel ----
__global__ __launch_bounds__(THREADS, 2)
void treelstm_mma(const float* __restrict__ ch_c,
                  const float* __restrict__ b_i, const float* __restrict__ b_o,
                  const float* __restrict__ b_u, const float* __restrict__ fbias,
                  float* __restrict__ out) {
    extern __shared__ char smem[];
    const uint32_t sbase = smem_u32(smem);
    const int tid  = threadIdx.x;
    const int wid  = tid >> 5, lane = tid & 31;
    const int wm   = wid & 1;          // 2 m-warps (32 rows each)
    const int wn   = wid >> 1;         // 4 n-warps (80 cols each)
    const int bht  = blockIdx.x;
    const int mt   = blockIdx.y;
    const int bh0  = bht * BHh;
    const int bm0  = mt * BM;

    const uint32_t STG0 = sbase;
    const uint32_t STG1 = sbase + STAGE_BYTES;
    const uint32_t mbF0 = sbase + 2 * STAGE_BYTES;        // full barriers (tx)
    const uint32_t mbF1 = mbF0 + 8;
    const uint32_t mbE0 = mbF0 + 16;                      // empty barriers (8 arrivals)
    const uint32_t mbE1 = mbF0 + 24;

    const char* Abase = reinterpret_cast<const char*>(g_Xt);
    const char* Bbase = reinterpret_cast<const char*>(g_Wt);
    auto Asrc = [&](int c) { return Abase + ((size_t)(c * 256 + mt)) * A_TILE; };
    auto Bsrc = [&](int c) { return Bbase + ((size_t)(c * 8 + bht)) * B_TILE; };

    if (tid == 0) {
        mbar_init(mbF0, 1);  mbar_init(mbF1, 1);
        mbar_init(mbE0, 8);  mbar_init(mbE1, 8);
    }
    __syncthreads();
    if (tid == 0) {
        mbar_expect(mbF0, STAGE_BYTES);
        bulk_cp(STG0 + OFF_A, Asrc(0), A_TILE, mbF0);
        bulk_cp(STG0 + OFF_B, Bsrc(0), B_TILE, mbF0);
        mbar_expect(mbF1, STAGE_BYTES);
        bulk_cp(STG1 + OFF_A, Asrc(1), A_TILE, mbF1);
        bulk_cp(STG1 + OFF_B, Bsrc(1), B_TILE, mbF1);
    }

    // ldmatrix lane addressing (granule-blocked, no swizzle)
    const int ar  = ((lane >> 3) & 1) * 8 + (lane & 7);
    const uint32_t aBase = (uint32_t)((wm * 32 + ar) * 16) + (uint32_t)(lane >> 4) * AG;
    const int br  = ((lane >> 4) & 1) * 8 + (lane & 7);
    const uint32_t bBase = (uint32_t)((wn * 80 + br) * 16) + (uint32_t)((lane >> 3) & 1) * BG;

    float acc[2][10][4];               // warp tile 32x80, fp32 masters
    #pragma unroll
    for (int mi = 0; mi < 2; mi++)
        #pragma unroll
        for (int ni = 0; ni < 10; ni++)
            #pragma unroll
            for (int q = 0; q < 4; q++) acc[mi][ni][q] = 0.0f;

    uint32_t phf0 = 0, phf1 = 0;       // per-warp full phases
    uint32_t phe0 = 0, phe1 = 0;       // producer-only empty phases

    // prologue: wait chunk 0, load its first fragments (carried across chunks)
    uint32_t A[2][8], Bf[2][4];
    mbar_wait(mbF0, phf0); phf0 ^= 1;
    ldsm4(A[0] + 0, STG0 + OFF_A + aBase);
    ldsm4(A[0] + 4, STG0 + OFF_A + aBase + 256);
    ldsm4(Bf[0],    STG0 + OFF_B + bBase);

    for (int k = 0; k < NCHUNK; k++) {
        const int s = k & 1;
        const uint32_t stg  = s ? STG1 : STG0;
        const uint32_t nstg = s ? STG0 : STG1;

        #pragma unroll
        for (int it = 0; it < 20; it++) {
            const int ks = it / 5, np = it % 5;
            const int ca = ks & 1, cb = it & 1;
            if (it < 19) {
                const int ks2 = (it + 1) / 5, np2 = (it + 1) % 5;
                ldsm4(Bf[1 - cb], stg + OFF_B + bBase
                                  + (uint32_t)(2 * ks2) * BG + (uint32_t)np2 * 256);
                if (np2 == 0) {
                    const uint32_t aA = stg + OFF_A + aBase + (uint32_t)(2 * ks2) * AG;
                    ldsm4(A[1 - ca] + 0, aA);
                    ldsm4(A[1 - ca] + 4, aA + 256);
                }
            } else if (k + 1 < NCHUNK) {
                // cross-chunk: wait next stage full (usually instant), prefetch
                // its first fragments into the continuing ping-pong slots.
                if (s) { mbar_wait(mbF0, phf0); phf0 ^= 1; }
                else   { mbar_wait(mbF1, phf1); phf1 ^= 1; }
                ldsm4(Bf[1 - cb], nstg + OFF_B + bBase);
                ldsm4(A[1 - ca] + 0, nstg + OFF_A + aBase);
                ldsm4(A[1 - ca] + 4, nstg + OFF_A + aBase + 256);
            }
            mma_f16(acc[0][np*2+0], A[ca] + 0, Bf[cb] + 0);
            mma_f16(acc[0][np*2+1], A[ca] + 0, Bf[cb] + 2);
            mma_f16(acc[1][np*2+0], A[ca] + 4, Bf[cb] + 0);
            mma_f16(acc[1][np*2+1], A[ca] + 4, Bf[cb] + 2);
        }
        // this warp is done reading stage s
        if (lane == 0) mbar_arrive(s ? mbE1 : mbE0);
        // producer: all 8 warps done -> refill stage s for chunk k+2
        if (tid == 0 && k + 2 < NCHUNK) {
            if (s) { mbar_wait(mbE1, phe1); phe1 ^= 1; }
            else   { mbar_wait(mbE0, phe0); phe0 ^= 1; }
            const uint32_t mb = s ? mbF1 : mbF0;
            mbar_expect(mb, STAGE_BYTES);
            bulk_cp(stg + OFF_A, Asrc(k + 2), A_TILE, mb);
            bulk_cp(stg + OFF_B, Bsrc(k + 2), B_TILE, mb);
        }
    }

    // ---- epilogue: recombine gates through SMEM ----
    __syncthreads();                    // all warps out of mainloop
    float* gbuf = reinterpret_cast<float*>(smem);   // [320][65] = 83KB, fits
    #pragma unroll
    for (int mi = 0; mi < 2; mi++)
        #pragma unroll
        for (int ni = 0; ni < 10; ni++) {
            const int m = wm * 32 + mi * 16 + (lane >> 2);
            const int n = wn * 80 + ni * 8 + 2 * (lane & 3);
            gbuf[(size_t)n * 65 + m]           = acc[mi][ni][0];
            gbuf[(size_t)(n + 1) * 65 + m]     = acc[mi][ni][1];
            gbuf[(size_t)n * 65 + m + 8]       = acc[mi][ni][2];
            gbuf[(size_t)(n + 1) * 65 + m + 8] = acc[mi][ni][3];
        }
    __syncthreads();

    for (int idx = tid; idx < BM * BHh; idx += THREADS) {
        const int m = idx >> 6, h = idx & 63;
        const int hg = bh0 + h;
        const int b  = bm0 + m;
        const float vi = gbuf[(size_t)(0 * 64 + h) * 65 + m];
        const float vo = gbuf[(size_t)(1 * 64 + h) * 65 + m];
        const float vu = gbuf[(size_t)(2 * 64 + h) * 65 + m];
        const float v0 = gbuf[(size_t)(3 * 64 + h) * 65 + m];
        const float v1 = gbuf[(size_t)(4 * 64 + h) * 65 + m];
        const float ig = sigmf(vi + __ldg(&b_i[hg]));
        const float og = sigmf(vo + __ldg(&b_o[hg]));
        const float ug = tanhf(vu + __ldg(&b_u[hg]));
        const float f0 = sigmf(v0);
        const float f1 = sigmf(v1);
        const float c0 = ch_c[(size_t)b * H + hg];
        const float c1 = ch_c[(size_t)(Bsz + b) * H + hg];
        const float fb = __ldg(&fbias[hg]);
        const float nc = fmaf(ig, ug, fmaf(f0, c0, fmaf(f1, c1, fb * (c0 + c1))));
        const size_t o = (size_t)b * H + hg;
        out[o] = nc;
        out[(size_t)Bsz * H + o] = tanhf(og * nc);
    }
}

extern "C" void kernel_launch(void* const* d_in, const int* in_sizes, int n_in,
                              void* d_out, int out_size) {
    const float* label = (const float*)d_in[0];
    const float* ch_h  = (const float*)d_in[1];
    const float* ch_c  = (const float*)d_in[2];
    const float* W_i   = (const float*)d_in[3];
    const float* b_i   = (const float*)d_in[4];
    const float* W_o   = (const float*)d_in[5];
    const float* b_o   = (const float*)d_in[6];
    const float* W_u   = (const float*)d_in[7];
    const float* b_u   = (const float*)d_in[8];
    const float* W_fl  = (const float*)d_in[9];
    const float* W_fs  = (const float*)d_in[10];
    const float* fb    = (const float*)d_in[11];

    pack_all<<<NXB + NWB, 256, PACK_SMEM>>>(label, ch_h, W_i, W_o, W_u, W_fl, W_fs);

    cudaFuncSetAttribute(treelstm_mma, cudaFuncAttributeMaxDynamicSharedMemorySize, SMEM_TOTAL);
    dim3 grid(H / BHh, Bsz / BM);   // (8, 256), 2 CTAs/SM
    treelstm_mma<<<grid, THREADS, SMEM_TOTAL>>>(ch_c, b_i, b_o, b_u, fb, (float*)d_out);
}